// round 1
// baseline (speedup 1.0000x reference)
#include <cuda_runtime.h>
#include <cstdint>
#include <cstddef>

// ---------------- problem constants ----------------
#define N_X    20000
#define N_GENE 4264
#define NN     24264        // N_X + N_GENE
#define EE     120000
#define NREL   4

#define IN1    1613
#define OUT1   1600
#define OUT2   900
#define OUT3   400

// Layer-1 combined-input width: [h | agg0..agg3] = 5*1613 = 8065, pad to /8
#define LD1    8072
#define K1     8072
// Layer-2: 5*1600 = 8000 (already /8)
#define LD2    8000
#define K2     8000
// MLP layer: K = 900 padded to 904
#define LDH2   904
#define K3     904

// ---------------- device scratch (no allocs allowed) ----------------
// +64 floats slack so float4 over-reads on the B-side stay in-buffer.
__device__ float gX1 [(size_t)NN * LD1 + 64];          // [N, 8072]  h | agg (layer1 input)
__device__ float gX2 [(size_t)NN * LD2 + 64];          // [N, 8000]  h1 | agg (layer2 input)
__device__ float gWc1[(size_t)K1 * OUT1 + 64];         // [8072, 1600] root1; W1[0..3]
__device__ float gWc2[(size_t)K2 * OUT2 + 64];         // [8000, 900]
__device__ float gH2 [(size_t)NN * LDH2 + 64];         // [N, 904]  (900 used)
__device__ float gWc3[(size_t)K3 * OUT3 + 64];         // [904, 400]
__device__ float gH3 [(size_t)NN * OUT3 + 64];         // [N, 400]
__device__ float gCnt[NREL * NN];                      // per-(rel,dst) edge counts
__device__ int   g_is64;

// ---------------- small utility kernels ----------------
__global__ void zero_k(float* __restrict__ p, size_t n4) {
    size_t i = (size_t)blockIdx.x * blockDim.x + threadIdx.x;
    size_t stride = (size_t)gridDim.x * blockDim.x;
    float4* q = (float4*)p;
    float4 z = make_float4(0.f, 0.f, 0.f, 0.f);
    for (; i < n4; i += stride) q[i] = z;
}

__global__ void copy_k(float* __restrict__ dst, const float* __restrict__ src, size_t n4) {
    size_t i = (size_t)blockIdx.x * blockDim.x + threadIdx.x;
    size_t stride = (size_t)gridDim.x * blockDim.x;
    const float4* s = (const float4*)src;
    float4* d = (float4*)dst;
    for (; i < n4; i += stride) d[i] = s[i];
}

// Detect whether edge tensors are int64 (odd 32-bit words of small nonneg
// int64 values are all zero) or int32.
__global__ void detect_k(const unsigned int* __restrict__ ei) {
    if (blockIdx.x == 0 && threadIdx.x == 0) {
        int is64 = 1;
        for (int i = 1; i < 256; i += 2)
            if (ei[i] != 0u) { is64 = 0; break; }
        g_is64 = is64;
    }
}

__device__ __forceinline__ int read_idx(const void* p, int i, int is64) {
    return is64 ? (int)((const long long*)p)[i] : ((const int*)p)[i];
}

// Count edges per (relation, dst)
__global__ void count_k(const void* __restrict__ ei, const void* __restrict__ et) {
    int e = blockIdx.x * blockDim.x + threadIdx.x;
    if (e >= EE) return;
    int is64 = g_is64;
    int r   = read_idx(et, e, is64);
    int dst = read_idx(ei, EE + e, is64);
    atomicAdd(&gCnt[r * NN + dst], 1.0f);
}

// Build h = concat(x, gene_emb) into cols [0, IN1) of X1
__global__ void build_h_k(const float* __restrict__ x, const float* __restrict__ ge) {
    int i = blockIdx.y;
    int k = blockIdx.x * blockDim.x + threadIdx.x;
    if (k >= IN1) return;
    float v = (i < N_X) ? x[(size_t)i * IN1 + k] : ge[(size_t)(i - N_X) * IN1 + k];
    gX1[(size_t)i * LD1 + k] = v;
}

// Scatter-mean aggregation in input space:
//   X[dst, aggOff + r*inW + k] += X[src, k] / max(cnt[r,dst],1)
__global__ void scatter_k(const void* __restrict__ ei, const void* __restrict__ et,
                          float* __restrict__ X, int ld, int inW, int aggOff) {
    int e = blockIdx.x;
    int is64 = g_is64;
    int src = read_idx(ei, e, is64);
    int dst = read_idx(ei, EE + e, is64);
    int r   = read_idx(et, e, is64);
    float scale = 1.0f / fmaxf(gCnt[r * NN + dst], 1.0f);
    const float* s = X + (size_t)src * ld;
    float*       d = X + (size_t)dst * ld + aggOff + r * inW;
    for (int k = threadIdx.x; k < inW; k += blockDim.x)
        atomicAdd(d + k, s[k] * scale);
}

// ---------------- tiled SGEMM: C = relu?(A[MxK] * B[KxN] + bias) ----------------
// BM=BN=128, BK=8, 8x8 per thread, 256 threads. K must be a multiple of 8 and
// pad regions of A/B must be zero. B float4 loads may over-read within-buffer
// slack for the last column tile; those lanes are discarded by the store guard.
__global__ __launch_bounds__(256) void sgemm_k(
    const float* __restrict__ A, int lda,
    const float* __restrict__ B, int ldb,
    const float* __restrict__ bias,
    float* __restrict__ C, int ldc,
    int M, int Ncols, int K, int doRelu)
{
    __shared__ float As[8][128];
    __shared__ float Bs[8][128];
    const int tid  = threadIdx.x;
    const int rowA = tid >> 1;
    const int colA = (tid & 1) << 2;
    const int rowB = tid >> 5;
    const int colB = (tid & 31) << 2;
    const int tr   = (tid >> 4) << 3;
    const int tc   = (tid & 15) << 3;

    const int gRowBase = blockIdx.y * 128;
    const int gColBase = blockIdx.x * 128;

    const bool aOk = (gRowBase + rowA) < M;
    const float* Ag = A + (size_t)(gRowBase + rowA) * lda + colA;
    const float* Bg = B + (size_t)rowB * ldb + gColBase + colB;
    const float4 z4 = make_float4(0.f, 0.f, 0.f, 0.f);

    float acc[8][8];
#pragma unroll
    for (int i = 0; i < 8; i++)
#pragma unroll
        for (int j = 0; j < 8; j++) acc[i][j] = 0.f;

    for (int k0 = 0; k0 < K; k0 += 8) {
        float4 a4 = aOk ? *(const float4*)(Ag + k0) : z4;
        float4 b4 = *(const float4*)(Bg + (size_t)k0 * ldb);
        As[colA + 0][rowA] = a4.x;
        As[colA + 1][rowA] = a4.y;
        As[colA + 2][rowA] = a4.z;
        As[colA + 3][rowA] = a4.w;
        *(float4*)&Bs[rowB][colB] = b4;
        __syncthreads();
#pragma unroll
        for (int kk = 0; kk < 8; kk++) {
            float4 ra0 = *(const float4*)&As[kk][tr];
            float4 ra1 = *(const float4*)&As[kk][tr + 4];
            float4 rb0 = *(const float4*)&Bs[kk][tc];
            float4 rb1 = *(const float4*)&Bs[kk][tc + 4];
            float ra[8] = {ra0.x, ra0.y, ra0.z, ra0.w, ra1.x, ra1.y, ra1.z, ra1.w};
            float rb[8] = {rb0.x, rb0.y, rb0.z, rb0.w, rb1.x, rb1.y, rb1.z, rb1.w};
#pragma unroll
            for (int i = 0; i < 8; i++)
#pragma unroll
                for (int j = 0; j < 8; j++)
                    acc[i][j] += ra[i] * rb[j];
        }
        __syncthreads();
    }

#pragma unroll
    for (int i = 0; i < 8; i++) {
        int gr = gRowBase + tr + i;
        if (gr >= M) continue;
#pragma unroll
        for (int j = 0; j < 8; j++) {
            int gc = gColBase + tc + j;
            if (gc < Ncols) {
                float v = acc[i][j] + bias[gc];
                if (doRelu) v = fmaxf(v, 0.f);
                C[(size_t)gr * ldc + gc] = v;
            }
        }
    }
}

// ---------------- final head: z = H3 @ lin2 + b; out = log_softmax(z) ----------------
__global__ void head_k(const float* __restrict__ lin2, const float* __restrict__ b,
                       float* __restrict__ out) {
    int row  = blockIdx.x * (blockDim.x >> 5) + (threadIdx.x >> 5);
    int lane = threadIdx.x & 31;
    if (row >= NN) return;
    const float* h = gH3 + (size_t)row * OUT3;
    float a0 = 0.f, a1 = 0.f;
    for (int k = lane; k < OUT3; k += 32) {
        float v = h[k];
        a0 += v * lin2[k * 2 + 0];
        a1 += v * lin2[k * 2 + 1];
    }
#pragma unroll
    for (int o = 16; o; o >>= 1) {
        a0 += __shfl_down_sync(0xffffffffu, a0, o);
        a1 += __shfl_down_sync(0xffffffffu, a1, o);
    }
    if (lane == 0) {
        a0 += b[0]; a1 += b[1];
        float m = fmaxf(a0, a1);
        float lse = m + logf(expf(a0 - m) + expf(a1 - m));
        out[row * 2 + 0] = a0 - lse;
        out[row * 2 + 1] = a1 - lse;
    }
}

// ---------------- host ----------------
static float* sym_addr(const void* s) {
    void* p = nullptr;
    cudaGetSymbolAddress(&p, s);
    return (float*)p;
}

extern "C" void kernel_launch(void* const* d_in, const int* in_sizes, int n_in,
                              void* d_out, int out_size) {
    const float* x        = (const float*)d_in[0];
    const void*  eidx     = d_in[1];
    const void*  etype    = d_in[2];
    const float* gene_emb = (const float*)d_in[3];
    const float* W1       = (const float*)d_in[4];
    const float* root1    = (const float*)d_in[5];
    const float* b1       = (const float*)d_in[6];
    const float* W2       = (const float*)d_in[7];
    const float* root2    = (const float*)d_in[8];
    const float* b2       = (const float*)d_in[9];
    const float* lin1_w   = (const float*)d_in[10];
    const float* lin1_b   = (const float*)d_in[11];
    const float* lin2_w   = (const float*)d_in[12];
    const float* lin2_b   = (const float*)d_in[13];
    float* out = (float*)d_out;

    float* X1  = sym_addr(gX1);
    float* X2  = sym_addr(gX2);
    float* Wc1 = sym_addr(gWc1);
    float* Wc2 = sym_addr(gWc2);
    float* H2  = sym_addr(gH2);
    float* Wc3 = sym_addr(gWc3);
    float* H3  = sym_addr(gH3);
    float* Cnt = sym_addr(gCnt);

    const int ZB = 1024, ZT = 256;

    // dtype detection for edge tensors
    detect_k<<<1, 1>>>((const unsigned int*)eidx);

    // counts
    zero_k<<<64, ZT>>>(Cnt, (size_t)(NREL * NN) / 4);
    count_k<<<(EE + 255) / 256, 256>>>(eidx, etype);

    // ---- layer 1 input assembly ----
    zero_k<<<ZB, ZT>>>(X1, ((size_t)NN * LD1 + 64) / 4);
    build_h_k<<<dim3((IN1 + 255) / 256, NN), 256>>>(x, gene_emb);
    zero_k<<<ZB, ZT>>>(Wc1, ((size_t)K1 * OUT1 + 64) / 4);
    copy_k<<<ZB, ZT>>>(Wc1, root1, (size_t)IN1 * OUT1 / 4);
    copy_k<<<ZB, ZT>>>(Wc1 + (size_t)IN1 * OUT1, W1, (size_t)NREL * IN1 * OUT1 / 4);
    scatter_k<<<EE, 256>>>(eidx, etype, X1, LD1, IN1, IN1);

    // ---- GEMM1 -> X2 cols [0,1600) with bias+relu ----
    zero_k<<<ZB, ZT>>>(X2, ((size_t)NN * LD2 + 64) / 4);
    {
        dim3 grid((OUT1 + 127) / 128, (NN + 127) / 128);
        sgemm_k<<<grid, 256>>>(X1, LD1, Wc1, OUT1, b1, X2, LD2, NN, OUT1, K1, 1);
    }

    // ---- layer 2 ----
    copy_k<<<ZB, ZT>>>(Wc2, root2, (size_t)OUT1 * OUT2 / 4);
    copy_k<<<ZB, ZT>>>(Wc2 + (size_t)OUT1 * OUT2, W2, (size_t)NREL * OUT1 * OUT2 / 4);
    scatter_k<<<EE, 256>>>(eidx, etype, X2, LD2, OUT1, OUT1);

    zero_k<<<ZB, ZT>>>(H2, ((size_t)NN * LDH2 + 64) / 4);
    {
        dim3 grid((OUT2 + 127) / 128, (NN + 127) / 128);
        sgemm_k<<<grid, 256>>>(X2, LD2, Wc2, OUT2, b2, H2, LDH2, NN, OUT2, K2, 1);
    }

    // ---- MLP lin1 ----
    zero_k<<<64, ZT>>>(Wc3, ((size_t)K3 * OUT3 + 64) / 4);
    copy_k<<<ZB, ZT>>>(Wc3, lin1_w, (size_t)OUT2 * OUT3 / 4);
    {
        dim3 grid((OUT3 + 127) / 128, (NN + 127) / 128);
        sgemm_k<<<grid, 256>>>(H2, LDH2, Wc3, OUT3, lin1_b, H3, OUT3, NN, OUT3, K3, 1);
    }

    // ---- lin2 + log_softmax ----
    head_k<<<(NN + 7) / 8, 256>>>(lin2_w, lin2_b, out);
}

// round 4
// speedup vs baseline: 1.6343x; 1.6343x over previous
#include <cuda_runtime.h>
#include <cuda_bf16.h>
#include <mma.h>
#include <cstdint>
#include <cstddef>

using namespace nvcuda;

// ---------------- problem constants ----------------
#define N_X    20000
#define N_GENE 4264
#define NN     24264
#define EE     120000
#define NREL   4

#define IN1    1613
#define OUT1   1600
#define OUT2   900
#define OUT3   400

#define LD1    8072      // fp32 X1 row stride (5*1613=8065 valid)
#define LD2    8000      // fp32 X2 row stride
#define LDH2   904       // fp32 H2 row stride (900 valid)

// bf16 GEMM K dims, multiples of 32
#define KP1    8128
#define KP2    8000
#define KP3    960

// ---------------- device scratch ----------------
__device__ float gX1 [(size_t)NN * LD1 + 64];
__device__ float gX2 [(size_t)NN * LD2 + 64];
__device__ float gH2 [(size_t)NN * LDH2 + 64];
__device__ float gH3 [(size_t)NN * OUT3 + 64];
__device__ float gCnt[NREL * NN];
__device__ int   g_is64;

__device__ __nv_bfloat16 gAh[(size_t)NN * KP1 + 64];
__device__ __nv_bfloat16 gAl[(size_t)NN * KP1 + 64];
__device__ __nv_bfloat16 gBh[(size_t)1600 * KP1 + 64];
__device__ __nv_bfloat16 gBl[(size_t)1600 * KP1 + 64];

// ---------------- small utility kernels ----------------
__global__ void zero_k(float* __restrict__ p, size_t n4) {
    size_t i = (size_t)blockIdx.x * blockDim.x + threadIdx.x;
    size_t stride = (size_t)gridDim.x * blockDim.x;
    float4* q = (float4*)p;
    float4 z = make_float4(0.f, 0.f, 0.f, 0.f);
    for (; i < n4; i += stride) q[i] = z;
}

__global__ void detect_k(const unsigned int* __restrict__ ei) {
    if (blockIdx.x == 0 && threadIdx.x == 0) {
        int is64 = 1;
        for (int i = 1; i < 256; i += 2)
            if (ei[i] != 0u) { is64 = 0; break; }
        g_is64 = is64;
    }
}

__device__ __forceinline__ int read_idx(const void* p, int i, int is64) {
    return is64 ? (int)((const long long*)p)[i] : ((const int*)p)[i];
}

__global__ void count_k(const void* __restrict__ ei, const void* __restrict__ et) {
    int e = blockIdx.x * blockDim.x + threadIdx.x;
    if (e >= EE) return;
    int is64 = g_is64;
    int r   = read_idx(et, e, is64);
    int dst = read_idx(ei, EE + e, is64);
    atomicAdd(&gCnt[r * NN + dst], 1.0f);
}

__global__ void build_h_k(const float* __restrict__ x, const float* __restrict__ ge) {
    int i = blockIdx.y;
    int k = blockIdx.x * blockDim.x + threadIdx.x;
    if (k >= IN1) return;
    float v = (i < N_X) ? x[(size_t)i * IN1 + k] : ge[(size_t)(i - N_X) * IN1 + k];
    gX1[(size_t)i * LD1 + k] = v;
}

__global__ void scatter_k(const void* __restrict__ ei, const void* __restrict__ et,
                          float* __restrict__ X, int ld, int inW, int aggOff) {
    int e = blockIdx.x;
    int is64 = g_is64;
    int src = read_idx(ei, e, is64);
    int dst = read_idx(ei, EE + e, is64);
    int r   = read_idx(et, e, is64);
    float scale = 1.0f / fmaxf(gCnt[r * NN + dst], 1.0f);
    const float* s = X + (size_t)src * ld;
    float*       d = X + (size_t)dst * ld + aggOff + r * inW;
    for (int k = threadIdx.x; k < inW; k += blockDim.x)
        atomicAdd(d + k, s[k] * scale);
}

// split fp32 activations -> bf16 hi/lo, with K zero-padding
__global__ void convx_k(const float* __restrict__ src, int lds, int srcW,
                        __nv_bfloat16* __restrict__ Dh, __nv_bfloat16* __restrict__ Dl, int ldd) {
    int r = blockIdx.y;
    int k = blockIdx.x * blockDim.x + threadIdx.x;
    if (k >= ldd) return;
    float v = (k < srcW) ? src[(size_t)r * lds + k] : 0.f;
    __nv_bfloat16 h = __float2bfloat16(v);
    __nv_bfloat16 l = __float2bfloat16(v - __bfloat162float(h));
    Dh[(size_t)r * ldd + k] = h;
    Dl[(size_t)r * ldd + k] = l;
}

// transpose+split weights: dst[n,k] K-major from root [inW x Nout] then W [4*inW x Nout]
__global__ void convw_k(const float* __restrict__ root, const float* __restrict__ W,
                        int Nout, int inW, __nv_bfloat16* __restrict__ Dh,
                        __nv_bfloat16* __restrict__ Dl, int ldd) {
    int n = blockIdx.y;
    int k = blockIdx.x * blockDim.x + threadIdx.x;
    if (k >= ldd) return;
    float v = 0.f;
    if (k < inW) v = root[(size_t)k * Nout + n];
    else if (k < 5 * inW) v = W[(size_t)(k - inW) * Nout + n];
    __nv_bfloat16 h = __float2bfloat16(v);
    __nv_bfloat16 l = __float2bfloat16(v - __bfloat162float(h));
    Dh[(size_t)n * ldd + k] = h;
    Dl[(size_t)n * ldd + k] = l;
}

__global__ void convw3_k(const float* __restrict__ lw,
                         __nv_bfloat16* __restrict__ Dh, __nv_bfloat16* __restrict__ Dl, int ldd) {
    int n = blockIdx.y;
    int k = blockIdx.x * blockDim.x + threadIdx.x;
    if (k >= ldd) return;
    float v = (k < OUT2) ? lw[(size_t)k * OUT3 + n] : 0.f;
    __nv_bfloat16 h = __float2bfloat16(v);
    __nv_bfloat16 l = __float2bfloat16(v - __bfloat162float(h));
    Dh[(size_t)n * ldd + k] = h;
    Dl[(size_t)n * ldd + k] = l;
}

// ---------------- WMMA bf16 GEMM with 3-term fp32 emulation ----------------
// C[M,Ncols] = relu?( A[M,Kpad] @ B[Ncols,Kpad]^T + bias ),
// accumulated as Ah@Bh + Ah@Bl + Al@Bh in fp32 fragments.
// CTA tile 128x128, BK=32, 3-stage cp.async pipeline, 8 warps (64x32 each).
#define GT     256
#define BK     32
#define LDS_K  48                       // padded K stride in elements (96B rows)
#define TILE_B (128 * LDS_K * 2)        // 12288 bytes per A or B tile
#define STAGE_B (2 * TILE_B)            // 24576
#define NSTAGE 3
#define EPI_LD 36                       // epilogue stride: 36 floats = 144B, mult of 16B
#define DSMEM  (NSTAGE * STAGE_B)       // 73728 (epilogue reuses this: 8*64*36*4 = 73728)

__device__ __forceinline__ void cp_async16(uint32_t dst, const void* src, bool ok) {
    int sz = ok ? 16 : 0;
    asm volatile("cp.async.cg.shared.global [%0], [%1], 16, %2;"
                 :: "r"(dst), "l"(src), "r"(sz));
}
__device__ __forceinline__ uint32_t smem_u32(const void* p) {
    uint32_t a;
    asm("{ .reg .u64 t; cvta.to.shared.u64 t, %1; cvt.u32.u64 %0, t; }" : "=r"(a) : "l"(p));
    return a;
}

__global__ __launch_bounds__(GT) void bfgemm_k(
    const __nv_bfloat16* __restrict__ Ah, const __nv_bfloat16* __restrict__ Al,
    const __nv_bfloat16* __restrict__ Bh, const __nv_bfloat16* __restrict__ Bl,
    const float* __restrict__ bias, float* __restrict__ C,
    int M, int Ncols, int Kpad, int ldc, int doRelu)
{
    extern __shared__ char dsm[];
    const uint32_t dsmU = smem_u32(dsm);

    const int tid = threadIdx.x;
    const int wid = tid >> 5;
    const int lane = tid & 31;
    const int warp_m = wid & 1;          // 0..1 -> 64-row slab
    const int warp_n = wid >> 1;         // 0..3 -> 32-col slab
    const int mbase = blockIdx.y * 128;
    const int nbase = blockIdx.x * 128;

    const int cpp = Kpad >> 5;           // BK-chunks per pass
    const int nChunks = 3 * cpp;

    wmma::fragment<wmma::accumulator, 16, 16, 16, float> cf[4][2];
#pragma unroll
    for (int i = 0; i < 4; i++)
#pragma unroll
        for (int j = 0; j < 2; j++) wmma::fill_fragment(cf[i][j], 0.f);

    // per-thread load slots: 2 for A, 2 for B
    const int arow0 = tid >> 1,            achk0 = (tid & 1);        // chunks 0..1
    const int arow1 = tid >> 1,            achk1 = (tid & 1) + 2;    // chunks 2..3

    auto issue = [&](int i) {
        const int s = i % NSTAGE;
        const int pass = i / cpp;
        const int k0 = (i - pass * cpp) << 5;
        const __nv_bfloat16* Ab = (pass < 2) ? Ah : Al;
        const __nv_bfloat16* Bb = (pass == 1) ? Bl : Bh;
        const uint32_t sA = dsmU + s * STAGE_B;
        const uint32_t sB = sA + TILE_B;
        // A tile: 128 rows x 32 bf16 = 4 x 16B chunks per row
        cp_async16(sA + arow0 * 96 + achk0 * 16,
                   Ab + (size_t)(mbase + arow0) * Kpad + k0 + achk0 * 8,
                   (mbase + arow0) < M);
        cp_async16(sA + arow1 * 96 + achk1 * 16,
                   Ab + (size_t)(mbase + arow1) * Kpad + k0 + achk1 * 8,
                   (mbase + arow1) < M);
        // B tile
        cp_async16(sB + arow0 * 96 + achk0 * 16,
                   Bb + (size_t)(nbase + arow0) * Kpad + k0 + achk0 * 8,
                   (nbase + arow0) < Ncols);
        cp_async16(sB + arow1 * 96 + achk1 * 16,
                   Bb + (size_t)(nbase + arow1) * Kpad + k0 + achk1 * 8,
                   (nbase + arow1) < Ncols);
        asm volatile("cp.async.commit_group;" ::: "memory");
    };

    issue(0);
    if (nChunks > 1) issue(1);

    for (int i = 0; i < nChunks; i++) {
        const int s = i % NSTAGE;
        asm volatile("cp.async.wait_group 1;" ::: "memory");
        __syncthreads();
        if (i + 2 < nChunks) issue(i + 2);

        const __nv_bfloat16* As = (const __nv_bfloat16*)(dsm + s * STAGE_B);
        const __nv_bfloat16* Bs = (const __nv_bfloat16*)(dsm + s * STAGE_B + TILE_B);
#pragma unroll
        for (int kk = 0; kk < 2; kk++) {
            wmma::fragment<wmma::matrix_a, 16, 16, 16, __nv_bfloat16, wmma::row_major> af[4];
            wmma::fragment<wmma::matrix_b, 16, 16, 16, __nv_bfloat16, wmma::col_major> bf[2];
#pragma unroll
            for (int mi = 0; mi < 4; mi++)
                wmma::load_matrix_sync(af[mi],
                    As + (warp_m * 64 + mi * 16) * LDS_K + kk * 16, LDS_K);
#pragma unroll
            for (int ni = 0; ni < 2; ni++)
                wmma::load_matrix_sync(bf[ni],
                    Bs + (warp_n * 32 + ni * 16) * LDS_K + kk * 16, LDS_K);
#pragma unroll
            for (int mi = 0; mi < 4; mi++)
#pragma unroll
                for (int ni = 0; ni < 2; ni++)
                    wmma::mma_sync(cf[mi][ni], af[mi], bf[ni], cf[mi][ni]);
        }
        __syncthreads();
    }
    asm volatile("cp.async.wait_group 0;" ::: "memory");
    __syncthreads();

    // epilogue: fragments -> smem (per-warp 64xEPI_LD region) -> bias+relu -> C
    float* epi = (float*)dsm + wid * 64 * EPI_LD;
#pragma unroll
    for (int mi = 0; mi < 4; mi++)
#pragma unroll
        for (int ni = 0; ni < 2; ni++)
            wmma::store_matrix_sync(epi + (mi * 16) * EPI_LD + ni * 16, cf[mi][ni],
                                    EPI_LD, wmma::mem_row_major);
    __syncwarp();

    const int gc = nbase + warp_n * 32 + lane;
    if (gc < Ncols) {
        const float bv = bias[gc];
        const int gr0 = mbase + warp_m * 64;
#pragma unroll 8
        for (int r = 0; r < 64; r++) {
            int gr = gr0 + r;
            if (gr < M) {
                float v = epi[r * EPI_LD + lane] + bv;
                if (doRelu) v = fmaxf(v, 0.f);
                C[(size_t)gr * ldc + gc] = v;
            }
        }
    }
}

// ---------------- final head ----------------
__global__ void head_k(const float* __restrict__ lin2, const float* __restrict__ b,
                       float* __restrict__ out) {
    int row  = blockIdx.x * (blockDim.x >> 5) + (threadIdx.x >> 5);
    int lane = threadIdx.x & 31;
    if (row >= NN) return;
    const float* h = gH3 + (size_t)row * OUT3;
    float a0 = 0.f, a1 = 0.f;
    for (int k = lane; k < OUT3; k += 32) {
        float v = h[k];
        a0 += v * lin2[k * 2 + 0];
        a1 += v * lin2[k * 2 + 1];
    }
#pragma unroll
    for (int o = 16; o; o >>= 1) {
        a0 += __shfl_down_sync(0xffffffffu, a0, o);
        a1 += __shfl_down_sync(0xffffffffu, a1, o);
    }
    if (lane == 0) {
        a0 += b[0]; a1 += b[1];
        float m = fmaxf(a0, a1);
        float lse = m + logf(expf(a0 - m) + expf(a1 - m));
        out[row * 2 + 0] = a0 - lse;
        out[row * 2 + 1] = a1 - lse;
    }
}

// ---------------- host ----------------
static float* sym_addr_f(const void* s) { void* p = nullptr; cudaGetSymbolAddress(&p, s); return (float*)p; }
static __nv_bfloat16* sym_addr_b(const void* s) { void* p = nullptr; cudaGetSymbolAddress(&p, s); return (__nv_bfloat16*)p; }

extern "C" void kernel_launch(void* const* d_in, const int* in_sizes, int n_in,
                              void* d_out, int out_size) {
    const float* x        = (const float*)d_in[0];
    const void*  eidx     = d_in[1];
    const void*  etype    = d_in[2];
    const float* gene_emb = (const float*)d_in[3];
    const float* W1       = (const float*)d_in[4];
    const float* root1    = (const float*)d_in[5];
    const float* b1       = (const float*)d_in[6];
    const float* W2       = (const float*)d_in[7];
    const float* root2    = (const float*)d_in[8];
    const float* b2       = (const float*)d_in[9];
    const float* lin1_w   = (const float*)d_in[10];
    const float* lin1_b   = (const float*)d_in[11];
    const float* lin2_w   = (const float*)d_in[12];
    const float* lin2_b   = (const float*)d_in[13];
    float* out = (float*)d_out;

    float* X1 = sym_addr_f(gX1);
    float* X2 = sym_addr_f(gX2);
    float* H2 = sym_addr_f(gH2);
    float* H3 = sym_addr_f(gH3);
    float* Cnt = sym_addr_f(gCnt);
    __nv_bfloat16* Ah = sym_addr_b(gAh);
    __nv_bfloat16* Al = sym_addr_b(gAl);
    __nv_bfloat16* Bh = sym_addr_b(gBh);
    __nv_bfloat16* Bl = sym_addr_b(gBl);

    static bool attr_done = false;
    if (!attr_done) {
        cudaFuncSetAttribute(bfgemm_k, cudaFuncAttributeMaxDynamicSharedMemorySize, DSMEM);
        attr_done = true;
    }

    const int ZT = 256;

    detect_k<<<1, 1>>>((const unsigned int*)eidx);
    zero_k<<<64, ZT>>>(Cnt, (size_t)(NREL * NN) / 4);
    count_k<<<(EE + 255) / 256, 256>>>(eidx, etype);

    // ---- layer 1 ----
    zero_k<<<1024, ZT>>>(X1, ((size_t)NN * LD1 + 64) / 4);
    build_h_k<<<dim3((IN1 + 255) / 256, NN), 256>>>(x, gene_emb);
    scatter_k<<<EE, 256>>>(eidx, etype, X1, LD1, IN1, IN1);

    convx_k<<<dim3((KP1 + 255) / 256, NN), 256>>>(X1, LD1, 5 * IN1, Ah, Al, KP1);
    convw_k<<<dim3((KP1 + 255) / 256, OUT1), 256>>>(root1, W1, OUT1, IN1, Bh, Bl, KP1);

    zero_k<<<1024, ZT>>>(X2, ((size_t)NN * LD2 + 64) / 4);
    {
        dim3 grid((OUT1 + 127) / 128, (NN + 127) / 128);
        bfgemm_k<<<grid, GT, DSMEM>>>(Ah, Al, Bh, Bl, b1, X2, NN, OUT1, KP1, LD2, 1);
    }

    // ---- layer 2 ----
    scatter_k<<<EE, 256>>>(eidx, etype, X2, LD2, OUT1, OUT1);
    convx_k<<<dim3((KP2 + 255) / 256, NN), 256>>>(X2, LD2, 5 * OUT1, Ah, Al, KP2);
    convw_k<<<dim3((KP2 + 255) / 256, OUT2), 256>>>(root2, W2, OUT2, OUT1, Bh, Bl, KP2);
    {
        dim3 grid((OUT2 + 127) / 128, (NN + 127) / 128);
        bfgemm_k<<<grid, GT, DSMEM>>>(Ah, Al, Bh, Bl, b2, H2, NN, OUT2, KP2, LDH2, 1);
    }

    // ---- MLP lin1 ----
    convx_k<<<dim3((KP3 + 255) / 256, NN), 256>>>(H2, LDH2, OUT2, Ah, Al, KP3);
    convw3_k<<<dim3((KP3 + 255) / 256, OUT3), 256>>>(lin1_w, Bh, Bl, KP3);
    {
        dim3 grid((OUT3 + 127) / 128, (NN + 127) / 128);
        bfgemm_k<<<grid, GT, DSMEM>>>(Ah, Al, Bh, Bl, lin1_b, H3, NN, OUT3, KP3, OUT3, 1);
    }

    // ---- lin2 + log_softmax ----
    head_k<<<(NN + 7) / 8, 256>>>(lin2_w, lin2_b, out);
}

// round 5
// speedup vs baseline: 1.7599x; 1.0768x over previous
#include <cuda_runtime.h>
#include <cuda_bf16.h>
#include <mma.h>
#include <cstdint>
#include <cstddef>

using namespace nvcuda;

// ---------------- problem constants ----------------
#define N_X    20000
#define N_GENE 4264
#define NN     24264
#define EE     120000
#define NREL   4

#define IN1    1613
#define OUT1   1600
#define OUT2   900
#define OUT3   400

#define LD1    8072      // fp32 X1 row stride (5*1613=8065 valid)
#define LD2    8000      // fp32 X2 row stride
#define LDH2   904       // fp32 H2 row stride (900 valid)

// bf16 GEMM K dims, multiples of 32
#define KP1    8128
#define KP2    8000
#define KP3    960

// ---------------- device scratch ----------------
__device__ float gX1 [(size_t)NN * LD1 + 64];
__device__ float gX2 [(size_t)NN * LD2 + 64];
__device__ float gH2 [(size_t)NN * LDH2 + 64];
__device__ float gH3 [(size_t)NN * OUT3 + 64];
__device__ float gCnt[NREL * NN];
__device__ int   g_is64;

__device__ __nv_bfloat16 gAh[(size_t)NN * KP1 + 64];
__device__ __nv_bfloat16 gAl[(size_t)NN * KP1 + 64];
__device__ __nv_bfloat16 gBh[(size_t)1600 * KP1 + 64];
__device__ __nv_bfloat16 gBl[(size_t)1600 * KP1 + 64];

// ---------------- small utility kernels ----------------
__global__ void zero_k(float* __restrict__ p, size_t n4) {
    size_t i = (size_t)blockIdx.x * blockDim.x + threadIdx.x;
    size_t stride = (size_t)gridDim.x * blockDim.x;
    float4* q = (float4*)p;
    float4 z = make_float4(0.f, 0.f, 0.f, 0.f);
    for (; i < n4; i += stride) q[i] = z;
}

__global__ void detect_k(const unsigned int* __restrict__ ei) {
    if (blockIdx.x == 0 && threadIdx.x == 0) {
        int is64 = 1;
        for (int i = 1; i < 256; i += 2)
            if (ei[i] != 0u) { is64 = 0; break; }
        g_is64 = is64;
    }
}

__device__ __forceinline__ int read_idx(const void* p, int i, int is64) {
    return is64 ? (int)((const long long*)p)[i] : ((const int*)p)[i];
}

__global__ void count_k(const void* __restrict__ ei, const void* __restrict__ et) {
    int e = blockIdx.x * blockDim.x + threadIdx.x;
    if (e >= EE) return;
    int is64 = g_is64;
    int r   = read_idx(et, e, is64);
    int dst = read_idx(ei, EE + e, is64);
    atomicAdd(&gCnt[r * NN + dst], 1.0f);
}

__global__ void build_h_k(const float* __restrict__ x, const float* __restrict__ ge) {
    int i = blockIdx.y;
    int k = blockIdx.x * blockDim.x + threadIdx.x;
    if (k >= IN1) return;
    float v = (i < N_X) ? x[(size_t)i * IN1 + k] : ge[(size_t)(i - N_X) * IN1 + k];
    gX1[(size_t)i * LD1 + k] = v;
}

__global__ void scatter_k(const void* __restrict__ ei, const void* __restrict__ et,
                          float* __restrict__ X, int ld, int inW, int aggOff) {
    int e = blockIdx.x;
    int is64 = g_is64;
    int src = read_idx(ei, e, is64);
    int dst = read_idx(ei, EE + e, is64);
    int r   = read_idx(et, e, is64);
    float scale = 1.0f / fmaxf(gCnt[r * NN + dst], 1.0f);
    const float* s = X + (size_t)src * ld;
    float*       d = X + (size_t)dst * ld + aggOff + r * inW;
    for (int k = threadIdx.x; k < inW; k += blockDim.x)
        atomicAdd(d + k, s[k] * scale);
}

// split fp32 activations -> bf16 hi/lo, with K zero-padding
__global__ void convx_k(const float* __restrict__ src, int lds, int srcW,
                        __nv_bfloat16* __restrict__ Dh, __nv_bfloat16* __restrict__ Dl, int ldd) {
    int r = blockIdx.y;
    int k = blockIdx.x * blockDim.x + threadIdx.x;
    if (k >= ldd) return;
    float v = (k < srcW) ? src[(size_t)r * lds + k] : 0.f;
    __nv_bfloat16 h = __float2bfloat16(v);
    __nv_bfloat16 l = __float2bfloat16(v - __bfloat162float(h));
    Dh[(size_t)r * ldd + k] = h;
    Dl[(size_t)r * ldd + k] = l;
}

// transpose+split weights: dst[n,k] K-major from root [inW x Nout] then W [4*inW x Nout]
__global__ void convw_k(const float* __restrict__ root, const float* __restrict__ W,
                        int Nout, int inW, __nv_bfloat16* __restrict__ Dh,
                        __nv_bfloat16* __restrict__ Dl, int ldd) {
    int n = blockIdx.y;
    int k = blockIdx.x * blockDim.x + threadIdx.x;
    if (k >= ldd) return;
    float v = 0.f;
    if (k < inW) v = root[(size_t)k * Nout + n];
    else if (k < 5 * inW) v = W[(size_t)(k - inW) * Nout + n];
    __nv_bfloat16 h = __float2bfloat16(v);
    __nv_bfloat16 l = __float2bfloat16(v - __bfloat162float(h));
    Dh[(size_t)n * ldd + k] = h;
    Dl[(size_t)n * ldd + k] = l;
}

__global__ void convw3_k(const float* __restrict__ lw,
                         __nv_bfloat16* __restrict__ Dh, __nv_bfloat16* __restrict__ Dl, int ldd) {
    int n = blockIdx.y;
    int k = blockIdx.x * blockDim.x + threadIdx.x;
    if (k >= ldd) return;
    float v = (k < OUT2) ? lw[(size_t)k * OUT3 + n] : 0.f;
    __nv_bfloat16 h = __float2bfloat16(v);
    __nv_bfloat16 l = __float2bfloat16(v - __bfloat162float(h));
    Dh[(size_t)n * ldd + k] = h;
    Dl[(size_t)n * ldd + k] = l;
}

// ---------------- WMMA bf16 GEMM, 3-term fp32 emulation, pass-fused ----------------
// C = relu?( A @ B^T + bias ), accumulated as Ah@Bh + Ah@Bl + Al@Bh per K-chunk
// from co-resident SMEM tiles. CTA tile 128x128, 4 warps (64x64 each), BK=32,
// 2-stage cp.async pipeline.
#define GT     128
#define BK     32
#define LDS_K  40                        // padded K stride (80B rows, 16B-mult)
#define TILE_B (128 * LDS_K * 2)         // 10240 B per tile
#define STAGE_B (4 * TILE_B)             // Ah|Al|Bh|Bl = 40960
#define NSTAGE 2
#define EPI_LD 68                        // 68 floats = 272B, mult of 16B
#define DSMEM  (NSTAGE * STAGE_B)        // 81920 (epilogue needs 4*64*68*4=69632)

__device__ __forceinline__ void cp_async16(uint32_t dst, const void* src, bool ok) {
    int sz = ok ? 16 : 0;
    asm volatile("cp.async.cg.shared.global [%0], [%1], 16, %2;"
                 :: "r"(dst), "l"(src), "r"(sz));
}
__device__ __forceinline__ uint32_t smem_u32(const void* p) {
    uint32_t a;
    asm("{ .reg .u64 t; cvta.to.shared.u64 t, %1; cvt.u32.u64 %0, t; }" : "=r"(a) : "l"(p));
    return a;
}

__global__ __launch_bounds__(GT) void bfgemm_k(
    const __nv_bfloat16* __restrict__ Ah, const __nv_bfloat16* __restrict__ Al,
    const __nv_bfloat16* __restrict__ Bh, const __nv_bfloat16* __restrict__ Bl,
    const float* __restrict__ bias, float* __restrict__ C,
    int M, int Ncols, int Kpad, int ldc, int doRelu)
{
    extern __shared__ char dsm[];
    const uint32_t dsmU = smem_u32(dsm);

    const int tid = threadIdx.x;
    const int wid = tid >> 5;
    const int lane = tid & 31;
    const int warp_m = wid & 1;           // 64-row slab
    const int warp_n = wid >> 1;          // 64-col slab
    const int mbase = blockIdx.y * 128;
    const int nbase = blockIdx.x * 128;

    const int nChunks = Kpad >> 5;

    wmma::fragment<wmma::accumulator, 16, 16, 16, float> cf[4][4];
#pragma unroll
    for (int i = 0; i < 4; i++)
#pragma unroll
        for (int j = 0; j < 4; j++) wmma::fill_fragment(cf[i][j], 0.f);

    const bool mOK = (mbase + tid) < M;
    const bool nOK = (nbase + tid) < Ncols;
    const __nv_bfloat16* pAh = Ah + (size_t)(mbase + tid) * Kpad;
    const __nv_bfloat16* pAl = Al + (size_t)(mbase + tid) * Kpad;
    const __nv_bfloat16* pBh = Bh + (size_t)(nbase + tid) * Kpad;
    const __nv_bfloat16* pBl = Bl + (size_t)(nbase + tid) * Kpad;

    auto issue = [&](int i) {
        const int s = i & 1;
        const int k0 = i << 5;
        const uint32_t st = dsmU + s * STAGE_B + tid * (LDS_K * 2);
#pragma unroll
        for (int c = 0; c < 4; c++) {
            cp_async16(st + 0 * TILE_B + c * 16, pAh + k0 + c * 8, mOK);
            cp_async16(st + 1 * TILE_B + c * 16, pAl + k0 + c * 8, mOK);
            cp_async16(st + 2 * TILE_B + c * 16, pBh + k0 + c * 8, nOK);
            cp_async16(st + 3 * TILE_B + c * 16, pBl + k0 + c * 8, nOK);
        }
        asm volatile("cp.async.commit_group;" ::: "memory");
    };

    issue(0);
    if (nChunks > 1) issue(1);

    const int arow = warp_m * 64;
    const int brow = warp_n * 64;

    for (int i = 0; i < nChunks; i++) {
        const int s = i & 1;
        if (i + 1 < nChunks)
            asm volatile("cp.async.wait_group 1;" ::: "memory");
        else
            asm volatile("cp.async.wait_group 0;" ::: "memory");
        __syncthreads();

        const __nv_bfloat16* sAh = (const __nv_bfloat16*)(dsm + s * STAGE_B);
        const __nv_bfloat16* sAl = (const __nv_bfloat16*)(dsm + s * STAGE_B + TILE_B);
        const __nv_bfloat16* sBh = (const __nv_bfloat16*)(dsm + s * STAGE_B + 2 * TILE_B);
        const __nv_bfloat16* sBl = (const __nv_bfloat16*)(dsm + s * STAGE_B + 3 * TILE_B);

#pragma unroll
        for (int kk = 0; kk < 2; kk++) {
            {   // phase 1: Ah x (Bh, Bl)
                wmma::fragment<wmma::matrix_a, 16, 16, 16, __nv_bfloat16, wmma::row_major> af[4];
#pragma unroll
                for (int mi = 0; mi < 4; mi++)
                    wmma::load_matrix_sync(af[mi], sAh + (arow + mi * 16) * LDS_K + kk * 16, LDS_K);
#pragma unroll
                for (int ni = 0; ni < 4; ni++) {
                    wmma::fragment<wmma::matrix_b, 16, 16, 16, __nv_bfloat16, wmma::col_major> bh;
                    wmma::load_matrix_sync(bh, sBh + (brow + ni * 16) * LDS_K + kk * 16, LDS_K);
#pragma unroll
                    for (int mi = 0; mi < 4; mi++)
                        wmma::mma_sync(cf[mi][ni], af[mi], bh, cf[mi][ni]);
                    wmma::fragment<wmma::matrix_b, 16, 16, 16, __nv_bfloat16, wmma::col_major> bl;
                    wmma::load_matrix_sync(bl, sBl + (brow + ni * 16) * LDS_K + kk * 16, LDS_K);
#pragma unroll
                    for (int mi = 0; mi < 4; mi++)
                        wmma::mma_sync(cf[mi][ni], af[mi], bl, cf[mi][ni]);
                }
            }
            {   // phase 2: Al x Bh
                wmma::fragment<wmma::matrix_a, 16, 16, 16, __nv_bfloat16, wmma::row_major> af[4];
#pragma unroll
                for (int mi = 0; mi < 4; mi++)
                    wmma::load_matrix_sync(af[mi], sAl + (arow + mi * 16) * LDS_K + kk * 16, LDS_K);
#pragma unroll
                for (int ni = 0; ni < 4; ni++) {
                    wmma::fragment<wmma::matrix_b, 16, 16, 16, __nv_bfloat16, wmma::col_major> bh;
                    wmma::load_matrix_sync(bh, sBh + (brow + ni * 16) * LDS_K + kk * 16, LDS_K);
#pragma unroll
                    for (int mi = 0; mi < 4; mi++)
                        wmma::mma_sync(cf[mi][ni], af[mi], bh, cf[mi][ni]);
                }
            }
        }
        __syncthreads();
        if (i + 2 < nChunks) issue(i + 2);
    }

    // epilogue: fragments -> smem (per-warp 64xEPI_LD) -> bias+relu -> C
    float* epi = (float*)dsm + wid * 64 * EPI_LD;
#pragma unroll
    for (int mi = 0; mi < 4; mi++)
#pragma unroll
        for (int ni = 0; ni < 4; ni++)
            wmma::store_matrix_sync(epi + (mi * 16) * EPI_LD + ni * 16, cf[mi][ni],
                                    EPI_LD, wmma::mem_row_major);
    __syncwarp();

    const int gc0 = nbase + warp_n * 64 + lane;
    const int gc1 = gc0 + 32;
    const bool c0ok = gc0 < Ncols, c1ok = gc1 < Ncols;
    const float bv0 = c0ok ? bias[gc0] : 0.f;
    const float bv1 = c1ok ? bias[gc1] : 0.f;
    const int gr0 = mbase + warp_m * 64;
#pragma unroll 8
    for (int r = 0; r < 64; r++) {
        int gr = gr0 + r;
        if (gr < M) {
            float v0 = epi[r * EPI_LD + lane] + bv0;
            float v1 = epi[r * EPI_LD + lane + 32] + bv1;
            if (doRelu) { v0 = fmaxf(v0, 0.f); v1 = fmaxf(v1, 0.f); }
            if (c0ok) C[(size_t)gr * ldc + gc0] = v0;
            if (c1ok) C[(size_t)gr * ldc + gc1] = v1;
        }
    }
}

// ---------------- final head ----------------
__global__ void head_k(const float* __restrict__ lin2, const float* __restrict__ b,
                       float* __restrict__ out) {
    int row  = blockIdx.x * (blockDim.x >> 5) + (threadIdx.x >> 5);
    int lane = threadIdx.x & 31;
    if (row >= NN) return;
    const float* h = gH3 + (size_t)row * OUT3;
    float a0 = 0.f, a1 = 0.f;
    for (int k = lane; k < OUT3; k += 32) {
        float v = h[k];
        a0 += v * lin2[k * 2 + 0];
        a1 += v * lin2[k * 2 + 1];
    }
#pragma unroll
    for (int o = 16; o; o >>= 1) {
        a0 += __shfl_down_sync(0xffffffffu, a0, o);
        a1 += __shfl_down_sync(0xffffffffu, a1, o);
    }
    if (lane == 0) {
        a0 += b[0]; a1 += b[1];
        float m = fmaxf(a0, a1);
        float lse = m + logf(expf(a0 - m) + expf(a1 - m));
        out[row * 2 + 0] = a0 - lse;
        out[row * 2 + 1] = a1 - lse;
    }
}

// ---------------- host ----------------
static float* sym_addr_f(const void* s) { void* p = nullptr; cudaGetSymbolAddress(&p, s); return (float*)p; }
static __nv_bfloat16* sym_addr_b(const void* s) { void* p = nullptr; cudaGetSymbolAddress(&p, s); return (__nv_bfloat16*)p; }

extern "C" void kernel_launch(void* const* d_in, const int* in_sizes, int n_in,
                              void* d_out, int out_size) {
    const float* x        = (const float*)d_in[0];
    const void*  eidx     = d_in[1];
    const void*  etype    = d_in[2];
    const float* gene_emb = (const float*)d_in[3];
    const float* W1       = (const float*)d_in[4];
    const float* root1    = (const float*)d_in[5];
    const float* b1       = (const float*)d_in[6];
    const float* W2       = (const float*)d_in[7];
    const float* root2    = (const float*)d_in[8];
    const float* b2       = (const float*)d_in[9];
    const float* lin1_w   = (const float*)d_in[10];
    const float* lin1_b   = (const float*)d_in[11];
    const float* lin2_w   = (const float*)d_in[12];
    const float* lin2_b   = (const float*)d_in[13];
    float* out = (float*)d_out;

    float* X1 = sym_addr_f(gX1);
    float* X2 = sym_addr_f(gX2);
    float* H2 = sym_addr_f(gH2);
    float* H3 = sym_addr_f(gH3);
    float* Cnt = sym_addr_f(gCnt);
    __nv_bfloat16* Ah = sym_addr_b(gAh);
    __nv_bfloat16* Al = sym_addr_b(gAl);
    __nv_bfloat16* Bh = sym_addr_b(gBh);
    __nv_bfloat16* Bl = sym_addr_b(gBl);

    static bool attr_done = false;
    if (!attr_done) {
        cudaFuncSetAttribute(bfgemm_k, cudaFuncAttributeMaxDynamicSharedMemorySize, DSMEM);
        attr_done = true;
    }

    const int ZT = 256;

    detect_k<<<1, 1>>>((const unsigned int*)eidx);
    zero_k<<<64, ZT>>>(Cnt, (size_t)(NREL * NN) / 4);
    count_k<<<(EE + 255) / 256, 256>>>(eidx, etype);

    // ---- layer 1 ----
    zero_k<<<1024, ZT>>>(X1, ((size_t)NN * LD1 + 64) / 4);
    build_h_k<<<dim3((IN1 + 255) / 256, NN), 256>>>(x, gene_emb);
    scatter_k<<<EE, 256>>>(eidx, etype, X1, LD1, IN1, IN1);

    convx_k<<<dim3((KP1 + 255) / 256, NN), 256>>>(X1, LD1, 5 * IN1, Ah, Al, KP1);
    convw_k<<<dim3((KP1 + 255) / 256, OUT1), 256>>>(root1, W1, OUT1, IN1, Bh, Bl, KP1);

    zero_k<<<1024, ZT>>>(X2, ((size_t)NN * LD2 + 64) / 4);
    {
        dim3 grid((OUT1 + 127) / 128, (NN + 127) / 128);
        bfgemm_k<<<grid, GT, DSMEM>>>(Ah, Al, Bh, Bl, b1, X2, NN, OUT1, KP1, LD2, 1);
    }

    // ---- layer 2 ----
    scatter_k<<<EE, 256>>>(eidx, etype, X2, LD2, OUT1, OUT1);
    convx_k<<<dim3((KP2 + 255) / 256, NN), 256>>>(X2, LD2, 5 * OUT1, Ah, Al, KP2);
    convw_k<<<dim3((KP2 + 255) / 256, OUT2), 256>>>(root2, W2, OUT2, OUT1, Bh, Bl, KP2);
    {
        dim3 grid((OUT2 + 127) / 128, (NN + 127) / 128);
        bfgemm_k<<<grid, GT, DSMEM>>>(Ah, Al, Bh, Bl, b2, H2, NN, OUT2, KP2, LDH2, 1);
    }

    // ---- MLP lin1 ----
    convx_k<<<dim3((KP3 + 255) / 256, NN), 256>>>(H2, LDH2, OUT2, Ah, Al, KP3);
    convw3_k<<<dim3((KP3 + 255) / 256, OUT3), 256>>>(lin1_w, Bh, Bl, KP3);
    {
        dim3 grid((OUT3 + 127) / 128, (NN + 127) / 128);
        bfgemm_k<<<grid, GT, DSMEM>>>(Ah, Al, Bh, Bl, lin1_b, H3, NN, OUT3, KP3, OUT3, 1);
    }

    // ---- lin2 + log_softmax ----
    head_k<<<(NN + 7) / 8, 256>>>(lin2_w, lin2_b, out);
}